// round 5
// baseline (speedup 1.0000x reference)
#include <cuda_runtime.h>
#include <cuda_fp16.h>
#include <math.h>
#include <cstdint>

#define EPS_BN 1e-3f

static constexpr int B_  = 4096;
static constexpr int TXN = 32;
static constexpr int SUB = 13;
static constexpr int R   = B_ * SUB;   // 53248 rows per tower

// -------------------- scratch (alloc-free: __device__ globals) --------------------
__device__ __half g_X [(size_t)2 * R * 64];      // layer-1 input (half)
__device__ float  g_Z [(size_t)2 * R * 64];      // layer-4 output (float)
__device__ __half g_A [(size_t)2 * R * 1024];    // h1 / h3
__device__ __half g_Bf[(size_t)2 * R * 512];     // h2
__device__ __half g_W1t[(size_t)2 * 1024 * 64];
__device__ __half g_W2t[(size_t)2 * 512 * 1024];
__device__ __half g_W3t[(size_t)2 * 512 * 512];
__device__ __half g_W4t[(size_t)2 * 64 * 512];

// -------------------- helpers --------------------
__device__ __forceinline__ uint32_t smem_u32(const void* p) {
    uint32_t a;
    asm("{ .reg .u64 t; cvta.to.shared.u64 t, %1; cvt.u32.u64 %0, t; }" : "=r"(a) : "l"(p));
    return a;
}
#define CP16(dst, src) \
    asm volatile("cp.async.cg.shared.global [%0], [%1], 16;" :: "r"(dst), "l"(src))
#define CP_COMMIT() asm volatile("cp.async.commit_group;" ::: "memory")

__device__ __forceinline__ void ldsm_x4(uint32_t& r0, uint32_t& r1, uint32_t& r2,
                                        uint32_t& r3, uint32_t addr) {
    asm volatile("ldmatrix.sync.aligned.m8n8.x4.shared.b16 {%0,%1,%2,%3}, [%4];"
        : "=r"(r0), "=r"(r1), "=r"(r2), "=r"(r3) : "r"(addr));
}
__device__ __forceinline__ void mma_f16(float& c0, float& c1, float& c2, float& c3,
                                        uint32_t a0, uint32_t a1, uint32_t a2, uint32_t a3,
                                        uint32_t b0, uint32_t b1) {
    asm volatile(
        "mma.sync.aligned.m16n8k16.row.col.f32.f16.f16.f32 "
        "{%0,%1,%2,%3}, {%4,%5,%6,%7}, {%8,%9}, {%0,%1,%2,%3};"
        : "+f"(c0), "+f"(c1), "+f"(c2), "+f"(c3)
        : "r"(a0), "r"(a1), "r"(a2), "r"(a3), "r"(b0), "r"(b1));
}

// -------------------- prologue: per-(b,s) input normalization --------------------
__global__ void norm_in_kernel(const float* __restrict__ V1,
                               const float* __restrict__ V2,
                               __half* __restrict__ X) {
    int pair = blockIdx.x;
    int b = pair / SUB, s = pair % SUB;
    int tid = threadIdx.x;
    int warp = tid >> 5, lane = tid & 31;
    const float* V = (warp == 0) ? V1 : V2;
    int base = ((b * TXN + lane) * SUB + s) * 2;
    float c0 = V[base], c1 = V[base + 1];
    float ss = c0 * c0 + c1 * c1;
    #pragma unroll
    for (int o = 16; o; o >>= 1) ss += __shfl_xor_sync(0xFFFFFFFFu, ss, o);
    float inv = rsqrtf(ss);
    X[((size_t)0 * R + pair) * 64 + tid] = __float2half_rn(c0 * inv);
    X[((size_t)1 * R + pair) * 64 + tid] = __float2half_rn(c1 * inv);
}

// -------------------- weight transpose: W[t][K][N] -> Wt[t][N][K] (half) ----------
__global__ void transpose_w(const float* __restrict__ W, __half* __restrict__ Wt,
                            int K, int N) {
    __shared__ float tile[32][33];
    int t = blockIdx.z;
    int k0 = blockIdx.y * 32, n0 = blockIdx.x * 32;
    const float* Wp = W + (size_t)t * K * N;
    __half* Wtp = Wt + (size_t)t * N * K;
    int x = threadIdx.x, y = threadIdx.y;   // 32 x 8
    #pragma unroll
    for (int dy = 0; dy < 32; dy += 8)
        tile[y + dy][x] = Wp[(size_t)(k0 + y + dy) * N + n0 + x];
    __syncthreads();
    #pragma unroll
    for (int dy = 0; dy < 32; dy += 8)
        Wtp[(size_t)(n0 + y + dy) * K + k0 + x] = __float2half_rn(tile[x][y + dy]);
}

// -------------------- FP16 mma GEMM + fused epilogue --------------------
// C[t][m][n] = epi( sum_k A[t][m][k] * Wt[t][n][k] )
// MODE 0: half( BN(relu(x+b)) )      MODE 1: float(x+b)
// 8 warps (2 x 4), warp tile 64 x (BN/4), 4-stage cp.async pipeline.
template <int BN, int MODE>
__global__ void __launch_bounds__(256, 1)
gemm_h(const __half* __restrict__ A, const __half* __restrict__ Wt,
       const float* __restrict__ bias, const float* __restrict__ gg,
       const float* __restrict__ bbe, const float* __restrict__ mm,
       const float* __restrict__ vv, void* __restrict__ Cv,
       int K, int N) {
    constexpr int BM = 128, BK = 64, STAGES = 4;
    constexpr int WN = BN / 4;              // warps 2 x 4
    constexpr int MT = 4;                   // 64 rows / 16
    constexpr int NT = WN / 8;
    constexpr int STG_A = BM * BK;          // halves
    constexpr int STG   = (BM + BN) * BK;   // halves per stage

    extern __shared__ __half smem[];
    const uint32_t sb = smem_u32(smem);

    const int tid  = threadIdx.x;
    const int wid  = tid >> 5, lane = tid & 31;
    const int grp  = lane >> 2, tig = lane & 3;
    const int wm   = wid & 1, wn = wid >> 1;
    const int t    = blockIdx.z;
    const int bm   = blockIdx.y * BM;
    const int bn   = blockIdx.x * BN;

    A  += (size_t)t * R * K;
    Wt += (size_t)t * N * K;
    bias += (size_t)t * N;
    if (MODE == 0) { gg += (size_t)t * N; bbe += (size_t)t * N; mm += (size_t)t * N; vv += (size_t)t * N; }

    const int iters = K / BK;

    // ---- async tile loader (XOR swizzle: 16B chunk c at row r -> c ^ (r&7))
    auto load_tiles = [&](int it) {
        const int k0 = it * BK;
        __half* d = smem + (it % STAGES) * STG;
        uint32_t dA = smem_u32(d), dB = dA + STG_A * 2;
        #pragma unroll
        for (int p = 0; p < 4; p++) {
            int idx = p * 256 + tid;
            int r = idx >> 3, c = idx & 7;
            CP16(dA + r * 128 + ((c ^ (r & 7)) << 4),
                 A + (size_t)(bm + r) * K + k0 + c * 8);
        }
        #pragma unroll
        for (int p = 0; p < BN / 32; p++) {
            int idx = p * 256 + tid;
            int r = idx >> 3, c = idx & 7;
            CP16(dB + r * 128 + ((c ^ (r & 7)) << 4),
                 Wt + (size_t)(bn + r) * K + k0 + c * 8);
        }
    };

    float acc[MT][NT][4];
    #pragma unroll
    for (int i = 0; i < MT; i++)
        #pragma unroll
        for (int j = 0; j < NT; j++)
            acc[i][j][0] = acc[i][j][1] = acc[i][j][2] = acc[i][j][3] = 0.f;

    // prologue: STAGES-1 committed groups (some may be empty)
    #pragma unroll
    for (int s = 0; s < STAGES - 1; s++) {
        if (s < iters) load_tiles(s);
        CP_COMMIT();
    }

    // precomputed ldmatrix lane roles
    const int a_row = wm * 64 + (lane & 7) + ((lane >> 3) & 1) * 8;  // + mi*16
    const int a_csel = lane >> 4;                                    // 0/1
    const int b_row = wn * WN + (lane & 7) + ((lane >> 4) & 1) * 8;  // + nb*16
    const int b_csel = (lane >> 3) & 1;

    for (int it = 0; it < iters; ++it) {
        asm volatile("cp.async.wait_group 2;" ::: "memory");
        __syncthreads();
        {
            int nxt = it + STAGES - 1;
            if (nxt < iters) load_tiles(nxt);
            CP_COMMIT();
        }

        const uint32_t aB = sb + (it % STAGES) * STG * 2;
        const uint32_t bB = aB + STG_A * 2;

        #pragma unroll
        for (int ks = 0; ks < BK / 16; ks++) {
            uint32_t af[MT][4], bf[NT][2];
            #pragma unroll
            for (int mi = 0; mi < MT; mi++) {
                int r = a_row + mi * 16;
                int c = ks * 2 + a_csel;
                ldsm_x4(af[mi][0], af[mi][1], af[mi][2], af[mi][3],
                        aB + r * 128 + ((c ^ (r & 7)) << 4));
            }
            #pragma unroll
            for (int nb = 0; nb < NT / 2; nb++) {
                int r = b_row + nb * 16;
                int c = ks * 2 + b_csel;
                ldsm_x4(bf[2 * nb][0], bf[2 * nb][1], bf[2 * nb + 1][0], bf[2 * nb + 1][1],
                        bB + r * 128 + ((c ^ (r & 7)) << 4));
            }
            #pragma unroll
            for (int mi = 0; mi < MT; mi++)
                #pragma unroll
                for (int ni = 0; ni < NT; ni++)
                    mma_f16(acc[mi][ni][0], acc[mi][ni][1], acc[mi][ni][2], acc[mi][ni][3],
                            af[mi][0], af[mi][1], af[mi][2], af[mi][3],
                            bf[ni][0], bf[ni][1]);
        }
    }

    // ---- epilogue
    #pragma unroll
    for (int ni = 0; ni < NT; ni++) {
        const int col = bn + wn * WN + ni * 8 + tig * 2;
        float pb0 = __ldg(&bias[col]), pb1 = __ldg(&bias[col + 1]);
        float pm0 = 0, pm1 = 0, ps0 = 0, ps1 = 0, pe0 = 0, pe1 = 0;
        if (MODE == 0) {
            pm0 = __ldg(&mm[col]);  pm1 = __ldg(&mm[col + 1]);
            ps0 = __ldg(&gg[col])     * rsqrtf(__ldg(&vv[col])     + EPS_BN);
            ps1 = __ldg(&gg[col + 1]) * rsqrtf(__ldg(&vv[col + 1]) + EPS_BN);
            pe0 = __ldg(&bbe[col]); pe1 = __ldg(&bbe[col + 1]);
        }
        #pragma unroll
        for (int mi = 0; mi < MT; mi++) {
            #pragma unroll
            for (int h = 0; h < 2; h++) {
                const int row = bm + wm * 64 + mi * 16 + grp + h * 8;
                float v0 = acc[mi][ni][h * 2 + 0] + pb0;
                float v1 = acc[mi][ni][h * 2 + 1] + pb1;
                if (MODE == 0) {
                    v0 = fmaxf(v0, 0.f); v1 = fmaxf(v1, 0.f);
                    v0 = (v0 - pm0) * ps0 + pe0;
                    v1 = (v1 - pm1) * ps1 + pe1;
                    __half2* cp = (__half2*)((__half*)Cv + (size_t)t * R * N
                                             + (size_t)row * N + col);
                    *cp = __floats2half2_rn(v0, v1);
                } else {
                    float2* cp = (float2*)((float*)Cv + (size_t)t * R * N
                                           + (size_t)row * N + col);
                    *cp = make_float2(v0, v1);
                }
            }
        }
    }
}

// -------------------- head: sigmoid + per-(b,s,ue) L2 norm + transpose ------------
__global__ void head_kernel(const float* __restrict__ Z, float* __restrict__ out) {
    int row = blockIdx.x;
    int o = threadIdx.x;            // 0..63, o = tx*2 + u
    int b = row / SUB, s = row % SUB;

    float vr = Z[(size_t)row * 64 + o];
    float zi = Z[((size_t)R + row) * 64 + o];
    float vi = 1.f / (1.f + expf(-zi));

    float p = vr * vr + vi * vi;
    #pragma unroll
    for (int off = 2; off < 32; off <<= 1)
        p += __shfl_xor_sync(0xFFFFFFFFu, p, off);

    __shared__ float partial[2][2];
    int lane = o & 31, warp = o >> 5;
    if (lane < 2) partial[warp][lane & 1] = p;
    __syncthreads();

    int u = o & 1, tx = o >> 1;
    float inv = rsqrtf(partial[0][u] + partial[1][u]);

    size_t ob = (((size_t)b * 64 + u * 32 + tx) * SUB + s) * 2;
    out[ob]     = vr * inv;
    out[ob + 1] = vi * inv;
}

// -------------------- launch --------------------
extern "C" void kernel_launch(void* const* d_in, const int* in_sizes, int n_in,
                              void* d_out, int out_size) {
    const float* V1  = (const float*)d_in[0];
    const float* V2  = (const float*)d_in[1];
    const float* W1  = (const float*)d_in[2];
    const float* b1  = (const float*)d_in[3];
    const float* g1  = (const float*)d_in[4];
    const float* be1 = (const float*)d_in[5];
    const float* m1  = (const float*)d_in[6];
    const float* v1  = (const float*)d_in[7];
    const float* W2  = (const float*)d_in[8];
    const float* b2  = (const float*)d_in[9];
    const float* g2  = (const float*)d_in[10];
    const float* be2 = (const float*)d_in[11];
    const float* m2  = (const float*)d_in[12];
    const float* v2  = (const float*)d_in[13];
    const float* W3  = (const float*)d_in[14];
    const float* b3  = (const float*)d_in[15];
    const float* g3  = (const float*)d_in[16];
    const float* be3 = (const float*)d_in[17];
    const float* m3  = (const float*)d_in[18];
    const float* v3  = (const float*)d_in[19];
    const float* W4  = (const float*)d_in[20];
    const float* b4  = (const float*)d_in[21];

    __half *X, *Abuf, *Bbuf, *W1t, *W2t, *W3t, *W4t;
    float *Z;
    cudaGetSymbolAddress((void**)&X,    g_X);
    cudaGetSymbolAddress((void**)&Z,    g_Z);
    cudaGetSymbolAddress((void**)&Abuf, g_A);
    cudaGetSymbolAddress((void**)&Bbuf, g_Bf);
    cudaGetSymbolAddress((void**)&W1t,  g_W1t);
    cudaGetSymbolAddress((void**)&W2t,  g_W2t);
    cudaGetSymbolAddress((void**)&W3t,  g_W3t);
    cudaGetSymbolAddress((void**)&W4t,  g_W4t);

    const int SMEM256 = (128 + 256) * 64 * 2 * 4;   // 196608
    const int SMEM64  = (128 +  64) * 64 * 2 * 4;   // 98304
    cudaFuncSetAttribute(gemm_h<256, 0>, cudaFuncAttributeMaxDynamicSharedMemorySize, SMEM256);
    cudaFuncSetAttribute(gemm_h<64, 1>,  cudaFuncAttributeMaxDynamicSharedMemorySize, SMEM64);

    norm_in_kernel<<<R, 64>>>(V1, V2, X);

    dim3 tb(32, 8);
    transpose_w<<<dim3(1024 / 32,   64 / 32, 2), tb>>>(W1, W1t,   64, 1024);
    transpose_w<<<dim3( 512 / 32, 1024 / 32, 2), tb>>>(W2, W2t, 1024,  512);
    transpose_w<<<dim3( 512 / 32,  512 / 32, 2), tb>>>(W3, W3t,  512,  512);
    transpose_w<<<dim3(  64 / 32,  512 / 32, 2), tb>>>(W4, W4t,  512,   64);

    gemm_h<256, 0><<<dim3(1024 / 256, R / 128, 2), 256, SMEM256>>>(
        X,    W1t, b1, g1, be1, m1, v1, Abuf, 64, 1024);
    gemm_h<256, 0><<<dim3(512 / 256, R / 128, 2), 256, SMEM256>>>(
        Abuf, W2t, b2, g2, be2, m2, v2, Bbuf, 1024, 512);
    gemm_h<256, 0><<<dim3(512 / 256, R / 128, 2), 256, SMEM256>>>(
        Bbuf, W3t, b3, g3, be3, m3, v3, Abuf, 512, 512);
    gemm_h<64, 1><<<dim3(1, R / 128, 2), 256, SMEM64>>>(
        Abuf, W4t, b4, nullptr, nullptr, nullptr, nullptr, Z, 512, 64);

    head_kernel<<<R, 64>>>(Z, (float*)d_out);
}

// round 6
// speedup vs baseline: 1.1348x; 1.1348x over previous
#include <cuda_runtime.h>
#include <cuda_fp16.h>
#include <math.h>
#include <cstdint>

#define EPS_BN 1e-3f

static constexpr int B_  = 4096;
static constexpr int TXN = 32;
static constexpr int SUB = 13;
static constexpr int R   = B_ * SUB;   // 53248 rows per tower

// -------------------- scratch (alloc-free: __device__ globals) --------------------
__device__ __half g_X [(size_t)2 * R * 64];      // layer-1 input (half)
__device__ float  g_Z [(size_t)2 * R * 64];      // layer-4 output (float)
__device__ __half g_A [(size_t)2 * R * 1024];    // h1 / h3
__device__ __half g_Bf[(size_t)2 * R * 512];     // h2
__device__ __half g_W1t[(size_t)2 * 1024 * 64];
__device__ __half g_W2t[(size_t)2 * 512 * 1024];
__device__ __half g_W3t[(size_t)2 * 512 * 512];
__device__ __half g_W4t[(size_t)2 * 64 * 512];

// -------------------- helpers --------------------
__device__ __forceinline__ uint32_t smem_u32(const void* p) {
    uint32_t a;
    asm("{ .reg .u64 t; cvta.to.shared.u64 t, %1; cvt.u32.u64 %0, t; }" : "=r"(a) : "l"(p));
    return a;
}
#define CP16(dst, src) \
    asm volatile("cp.async.cg.shared.global [%0], [%1], 16;" :: "r"(dst), "l"(src))
#define CP_COMMIT() asm volatile("cp.async.commit_group;" ::: "memory")

__device__ __forceinline__ void ldsm_x4(uint32_t& r0, uint32_t& r1, uint32_t& r2,
                                        uint32_t& r3, uint32_t addr) {
    asm volatile("ldmatrix.sync.aligned.m8n8.x4.shared.b16 {%0,%1,%2,%3}, [%4];"
        : "=r"(r0), "=r"(r1), "=r"(r2), "=r"(r3) : "r"(addr));
}
__device__ __forceinline__ void mma_f16(float& c0, float& c1, float& c2, float& c3,
                                        uint32_t a0, uint32_t a1, uint32_t a2, uint32_t a3,
                                        uint32_t b0, uint32_t b1) {
    asm volatile(
        "mma.sync.aligned.m16n8k16.row.col.f32.f16.f16.f32 "
        "{%0,%1,%2,%3}, {%4,%5,%6,%7}, {%8,%9}, {%0,%1,%2,%3};"
        : "+f"(c0), "+f"(c1), "+f"(c2), "+f"(c3)
        : "r"(a0), "r"(a1), "r"(a2), "r"(a3), "r"(b0), "r"(b1));
}

// -------------------- prologue: per-(b,s) input normalization --------------------
__global__ void norm_in_kernel(const float* __restrict__ V1,
                               const float* __restrict__ V2,
                               __half* __restrict__ X) {
    int pair = blockIdx.x;
    int b = pair / SUB, s = pair % SUB;
    int tid = threadIdx.x;
    int warp = tid >> 5, lane = tid & 31;
    const float* V = (warp == 0) ? V1 : V2;
    int base = ((b * TXN + lane) * SUB + s) * 2;
    float c0 = V[base], c1 = V[base + 1];
    float ss = c0 * c0 + c1 * c1;
    #pragma unroll
    for (int o = 16; o; o >>= 1) ss += __shfl_xor_sync(0xFFFFFFFFu, ss, o);
    float inv = rsqrtf(ss);
    X[((size_t)0 * R + pair) * 64 + tid] = __float2half_rn(c0 * inv);
    X[((size_t)1 * R + pair) * 64 + tid] = __float2half_rn(c1 * inv);
}

// -------------------- weight transpose: W[t][K][N] -> Wt[t][N][K] (half) ----------
__global__ void transpose_w(const float* __restrict__ W, __half* __restrict__ Wt,
                            int K, int N) {
    __shared__ float tile[32][33];
    int t = blockIdx.z;
    int k0 = blockIdx.y * 32, n0 = blockIdx.x * 32;
    const float* Wp = W + (size_t)t * K * N;
    __half* Wtp = Wt + (size_t)t * N * K;
    int x = threadIdx.x, y = threadIdx.y;   // 32 x 8
    #pragma unroll
    for (int dy = 0; dy < 32; dy += 8)
        tile[y + dy][x] = Wp[(size_t)(k0 + y + dy) * N + n0 + x];
    __syncthreads();
    #pragma unroll
    for (int dy = 0; dy < 32; dy += 8)
        Wtp[(size_t)(n0 + y + dy) * K + k0 + x] = __float2half_rn(tile[x][y + dy]);
}

// -------------------- FP16 mma GEMM + fused epilogue --------------------
// C[t][m][n] = epi( sum_k A[t][m][k] * Wt[t][n][k] )
// MODE 0: half( BN(relu(x+b)) )      MODE 1: float(x+b)
// 4 warps (2 x 2), warp tile 64 x (BN/2), 3-stage cp.async pipeline, 128 threads.
template <int BN, int MODE>
__global__ void __launch_bounds__(128, 2)
gemm_h(const __half* __restrict__ A, const __half* __restrict__ Wt,
       const float* __restrict__ bias, const float* __restrict__ gg,
       const float* __restrict__ bbe, const float* __restrict__ mm,
       const float* __restrict__ vv, void* __restrict__ Cv,
       int K, int N) {
    constexpr int BM = 128, BK = 64, STAGES = 3;
    constexpr int WN = BN / 2;              // warps 2 x 2
    constexpr int MT = 4;                   // 64 rows / 16
    constexpr int NT = WN / 8;
    constexpr int STG_A = BM * BK;          // halves
    constexpr int STG   = (BM + BN) * BK;   // halves per stage

    extern __shared__ __half smem[];
    const uint32_t sb = smem_u32(smem);

    const int tid  = threadIdx.x;
    const int wid  = tid >> 5, lane = tid & 31;
    const int grp  = lane >> 2, tig = lane & 3;
    const int wm   = wid & 1, wn = wid >> 1;
    const int t    = blockIdx.z;
    const int bm   = blockIdx.y * BM;
    const int bn   = blockIdx.x * BN;

    A  += (size_t)t * R * K;
    Wt += (size_t)t * N * K;
    bias += (size_t)t * N;
    if (MODE == 0) { gg += (size_t)t * N; bbe += (size_t)t * N; mm += (size_t)t * N; vv += (size_t)t * N; }

    const int iters = K / BK;

    // ---- async tile loader (XOR swizzle: 16B chunk c at row r -> c ^ (r&7))
    auto load_tiles = [&](int it) {
        const int k0 = it * BK;
        __half* d = smem + (it % STAGES) * STG;
        uint32_t dA = smem_u32(d), dB = dA + STG_A * 2;
        #pragma unroll
        for (int p = 0; p < 8; p++) {
            int idx = p * 128 + tid;
            int r = idx >> 3, c = idx & 7;
            CP16(dA + r * 128 + ((c ^ (r & 7)) << 4),
                 A + (size_t)(bm + r) * K + k0 + c * 8);
        }
        #pragma unroll
        for (int p = 0; p < BN / 16; p++) {
            int idx = p * 128 + tid;
            int r = idx >> 3, c = idx & 7;
            CP16(dB + r * 128 + ((c ^ (r & 7)) << 4),
                 Wt + (size_t)(bn + r) * K + k0 + c * 8);
        }
    };

    float acc[MT][NT][4];
    #pragma unroll
    for (int i = 0; i < MT; i++)
        #pragma unroll
        for (int j = 0; j < NT; j++)
            acc[i][j][0] = acc[i][j][1] = acc[i][j][2] = acc[i][j][3] = 0.f;

    // prologue: STAGES-1 committed groups (some may be empty)
    #pragma unroll
    for (int s = 0; s < STAGES - 1; s++) {
        if (s < iters) load_tiles(s);
        CP_COMMIT();
    }

    // precomputed ldmatrix lane roles
    const int a_row = wm * 64 + (lane & 7) + ((lane >> 3) & 1) * 8;  // + mi*16
    const int a_csel = lane >> 4;                                    // 0/1
    const int b_row = wn * WN + (lane & 7) + ((lane >> 4) & 1) * 8;  // + nb*16
    const int b_csel = (lane >> 3) & 1;

    for (int it = 0; it < iters; ++it) {
        asm volatile("cp.async.wait_group 1;" ::: "memory");
        __syncthreads();
        {
            int nxt = it + STAGES - 1;
            if (nxt < iters) load_tiles(nxt);
            CP_COMMIT();
        }

        const uint32_t aB = sb + (it % STAGES) * STG * 2;
        const uint32_t bB = aB + STG_A * 2;

        #pragma unroll
        for (int ks = 0; ks < BK / 16; ks++) {
            uint32_t af[MT][4], bf[NT][2];
            #pragma unroll
            for (int mi = 0; mi < MT; mi++) {
                int r = a_row + mi * 16;
                int c = ks * 2 + a_csel;
                ldsm_x4(af[mi][0], af[mi][1], af[mi][2], af[mi][3],
                        aB + r * 128 + ((c ^ (r & 7)) << 4));
            }
            #pragma unroll
            for (int nb = 0; nb < NT / 2; nb++) {
                int r = b_row + nb * 16;
                int c = ks * 2 + b_csel;
                ldsm_x4(bf[2 * nb][0], bf[2 * nb][1], bf[2 * nb + 1][0], bf[2 * nb + 1][1],
                        bB + r * 128 + ((c ^ (r & 7)) << 4));
            }
            #pragma unroll
            for (int mi = 0; mi < MT; mi++)
                #pragma unroll
                for (int ni = 0; ni < NT; ni++)
                    mma_f16(acc[mi][ni][0], acc[mi][ni][1], acc[mi][ni][2], acc[mi][ni][3],
                            af[mi][0], af[mi][1], af[mi][2], af[mi][3],
                            bf[ni][0], bf[ni][1]);
        }
    }

    // ---- epilogue
    #pragma unroll
    for (int ni = 0; ni < NT; ni++) {
        const int col = bn + wn * WN + ni * 8 + tig * 2;
        float pb0 = __ldg(&bias[col]), pb1 = __ldg(&bias[col + 1]);
        float pm0 = 0, pm1 = 0, ps0 = 0, ps1 = 0, pe0 = 0, pe1 = 0;
        if (MODE == 0) {
            pm0 = __ldg(&mm[col]);  pm1 = __ldg(&mm[col + 1]);
            ps0 = __ldg(&gg[col])     * rsqrtf(__ldg(&vv[col])     + EPS_BN);
            ps1 = __ldg(&gg[col + 1]) * rsqrtf(__ldg(&vv[col + 1]) + EPS_BN);
            pe0 = __ldg(&bbe[col]); pe1 = __ldg(&bbe[col + 1]);
        }
        #pragma unroll
        for (int mi = 0; mi < MT; mi++) {
            #pragma unroll
            for (int h = 0; h < 2; h++) {
                const int row = bm + wm * 64 + mi * 16 + grp + h * 8;
                float v0 = acc[mi][ni][h * 2 + 0] + pb0;
                float v1 = acc[mi][ni][h * 2 + 1] + pb1;
                if (MODE == 0) {
                    v0 = fmaxf(v0, 0.f); v1 = fmaxf(v1, 0.f);
                    v0 = (v0 - pm0) * ps0 + pe0;
                    v1 = (v1 - pm1) * ps1 + pe1;
                    __half2* cp = (__half2*)((__half*)Cv + (size_t)t * R * N
                                             + (size_t)row * N + col);
                    *cp = __floats2half2_rn(v0, v1);
                } else {
                    float2* cp = (float2*)((float*)Cv + (size_t)t * R * N
                                           + (size_t)row * N + col);
                    *cp = make_float2(v0, v1);
                }
            }
        }
    }
}

// -------------------- head: sigmoid + per-(b,s,ue) L2 norm + transpose ------------
__global__ void head_kernel(const float* __restrict__ Z, float* __restrict__ out) {
    int row = blockIdx.x;
    int o = threadIdx.x;            // 0..63, o = tx*2 + u
    int b = row / SUB, s = row % SUB;

    float vr = Z[(size_t)row * 64 + o];
    float zi = Z[((size_t)R + row) * 64 + o];
    float vi = 1.f / (1.f + expf(-zi));

    float p = vr * vr + vi * vi;
    #pragma unroll
    for (int off = 2; off < 32; off <<= 1)
        p += __shfl_xor_sync(0xFFFFFFFFu, p, off);

    __shared__ float partial[2][2];
    int lane = o & 31, warp = o >> 5;
    if (lane < 2) partial[warp][lane & 1] = p;
    __syncthreads();

    int u = o & 1, tx = o >> 1;
    float inv = rsqrtf(partial[0][u] + partial[1][u]);

    size_t ob = (((size_t)b * 64 + u * 32 + tx) * SUB + s) * 2;
    out[ob]     = vr * inv;
    out[ob + 1] = vi * inv;
}

// -------------------- launch --------------------
extern "C" void kernel_launch(void* const* d_in, const int* in_sizes, int n_in,
                              void* d_out, int out_size) {
    const float* V1  = (const float*)d_in[0];
    const float* V2  = (const float*)d_in[1];
    const float* W1  = (const float*)d_in[2];
    const float* b1  = (const float*)d_in[3];
    const float* g1  = (const float*)d_in[4];
    const float* be1 = (const float*)d_in[5];
    const float* m1  = (const float*)d_in[6];
    const float* v1  = (const float*)d_in[7];
    const float* W2  = (const float*)d_in[8];
    const float* b2  = (const float*)d_in[9];
    const float* g2  = (const float*)d_in[10];
    const float* be2 = (const float*)d_in[11];
    const float* m2  = (const float*)d_in[12];
    const float* v2  = (const float*)d_in[13];
    const float* W3  = (const float*)d_in[14];
    const float* b3  = (const float*)d_in[15];
    const float* g3  = (const float*)d_in[16];
    const float* be3 = (const float*)d_in[17];
    const float* m3  = (const float*)d_in[18];
    const float* v3  = (const float*)d_in[19];
    const float* W4  = (const float*)d_in[20];
    const float* b4  = (const float*)d_in[21];

    __half *X, *Abuf, *Bbuf, *W1t, *W2t, *W3t, *W4t;
    float *Z;
    cudaGetSymbolAddress((void**)&X,    g_X);
    cudaGetSymbolAddress((void**)&Z,    g_Z);
    cudaGetSymbolAddress((void**)&Abuf, g_A);
    cudaGetSymbolAddress((void**)&Bbuf, g_Bf);
    cudaGetSymbolAddress((void**)&W1t,  g_W1t);
    cudaGetSymbolAddress((void**)&W2t,  g_W2t);
    cudaGetSymbolAddress((void**)&W3t,  g_W3t);
    cudaGetSymbolAddress((void**)&W4t,  g_W4t);

    const int SMEM128 = (128 + 128) * 64 * 2 * 3;   // 98304
    const int SMEM64  = (128 +  64) * 64 * 2 * 3;   // 73728
    cudaFuncSetAttribute(gemm_h<128, 0>, cudaFuncAttributeMaxDynamicSharedMemorySize, SMEM128);
    cudaFuncSetAttribute(gemm_h<64, 1>,  cudaFuncAttributeMaxDynamicSharedMemorySize, SMEM64);

    norm_in_kernel<<<R, 64>>>(V1, V2, X);

    dim3 tb(32, 8);
    transpose_w<<<dim3(1024 / 32,   64 / 32, 2), tb>>>(W1, W1t,   64, 1024);
    transpose_w<<<dim3( 512 / 32, 1024 / 32, 2), tb>>>(W2, W2t, 1024,  512);
    transpose_w<<<dim3( 512 / 32,  512 / 32, 2), tb>>>(W3, W3t,  512,  512);
    transpose_w<<<dim3(  64 / 32,  512 / 32, 2), tb>>>(W4, W4t,  512,   64);

    gemm_h<128, 0><<<dim3(1024 / 128, R / 128, 2), 128, SMEM128>>>(
        X,    W1t, b1, g1, be1, m1, v1, Abuf, 64, 1024);
    gemm_h<128, 0><<<dim3(512 / 128, R / 128, 2), 128, SMEM128>>>(
        Abuf, W2t, b2, g2, be2, m2, v2, Bbuf, 1024, 512);
    gemm_h<128, 0><<<dim3(512 / 128, R / 128, 2), 128, SMEM128>>>(
        Bbuf, W3t, b3, g3, be3, m3, v3, Abuf, 512, 512);
    gemm_h<64, 1><<<dim3(1, R / 128, 2), 128, SMEM64>>>(
        Abuf, W4t, b4, nullptr, nullptr, nullptr, nullptr, Z, 512, 64);

    head_kernel<<<R, 64>>>(Z, (float*)d_out);
}

// round 7
// speedup vs baseline: 1.1641x; 1.0258x over previous
#include <cuda_runtime.h>
#include <cuda_fp16.h>
#include <math.h>
#include <cstdint>

#define EPS_BN 1e-3f

static constexpr int B_  = 4096;
static constexpr int TXN = 32;
static constexpr int SUB = 13;
static constexpr int R   = B_ * SUB;   // 53248 rows per tower

// -------------------- scratch (alloc-free: __device__ globals) --------------------
__device__ __half g_X [(size_t)2 * R * 64];
__device__ float  g_Z [(size_t)2 * R * 64];
__device__ __half g_A [(size_t)2 * R * 1024];
__device__ __half g_Bf[(size_t)2 * R * 512];
__device__ __half g_W1t[(size_t)2 * 1024 * 64];
__device__ __half g_W2t[(size_t)2 * 512 * 1024];
__device__ __half g_W3t[(size_t)2 * 512 * 512];
__device__ __half g_W4t[(size_t)2 * 64 * 512];

// -------------------- helpers --------------------
__device__ __forceinline__ uint32_t smem_u32(const void* p) {
    uint32_t a;
    asm("{ .reg .u64 t; cvta.to.shared.u64 t, %1; cvt.u32.u64 %0, t; }" : "=r"(a) : "l"(p));
    return a;
}
#define CP16(dst, src) \
    asm volatile("cp.async.cg.shared.global [%0], [%1], 16;" :: "r"(dst), "l"(src))
#define CP_COMMIT() asm volatile("cp.async.commit_group;" ::: "memory")

__device__ __forceinline__ void ldsm_x4(uint32_t& r0, uint32_t& r1, uint32_t& r2,
                                        uint32_t& r3, uint32_t addr) {
    asm volatile("ldmatrix.sync.aligned.m8n8.x4.shared.b16 {%0,%1,%2,%3}, [%4];"
        : "=r"(r0), "=r"(r1), "=r"(r2), "=r"(r3) : "r"(addr));
}
__device__ __forceinline__ void mma_f16(float& c0, float& c1, float& c2, float& c3,
                                        uint32_t a0, uint32_t a1, uint32_t a2, uint32_t a3,
                                        uint32_t b0, uint32_t b1) {
    asm volatile(
        "mma.sync.aligned.m16n8k16.row.col.f32.f16.f16.f32 "
        "{%0,%1,%2,%3}, {%4,%5,%6,%7}, {%8,%9}, {%0,%1,%2,%3};"
        : "+f"(c0), "+f"(c1), "+f"(c2), "+f"(c3)
        : "r"(a0), "r"(a1), "r"(a2), "r"(a3), "r"(b0), "r"(b1));
}

// -------------------- prologue: per-(b,s) input normalization (4 pairs/block) -----
__global__ void norm_in_kernel(const float* __restrict__ V1,
                               const float* __restrict__ V2,
                               __half* __restrict__ X) {
    int sub = threadIdx.x >> 6;                 // 0..3  (pair within block)
    int pair = blockIdx.x * 4 + sub;
    int b = pair / SUB, s = pair % SUB;
    int o = threadIdx.x & 63;
    int warp = o >> 5, lane = o & 31;
    const float* V = (warp == 0) ? V1 : V2;
    int base = ((b * TXN + lane) * SUB + s) * 2;
    float c0 = V[base], c1 = V[base + 1];
    float ss = c0 * c0 + c1 * c1;
    #pragma unroll
    for (int off = 16; off; off >>= 1) ss += __shfl_xor_sync(0xFFFFFFFFu, ss, off);
    float inv = rsqrtf(ss);
    X[((size_t)0 * R + pair) * 64 + o] = __float2half_rn(c0 * inv);
    X[((size_t)1 * R + pair) * 64 + o] = __float2half_rn(c1 * inv);
}

// -------------------- merged weight transpose (all 4 layers, one launch) ----------
__global__ void transpose_all(const float* __restrict__ W1, const float* __restrict__ W2,
                              const float* __restrict__ W3, const float* __restrict__ W4,
                              __half* __restrict__ W1t, __half* __restrict__ W2t,
                              __half* __restrict__ W3t, __half* __restrict__ W4t) {
    __shared__ float tile[32][33];
    int bid = blockIdx.x, t = blockIdx.z;
    const float* W; __half* Wt; int K, N, rem;
    if (bid < 64)       { W = W1; Wt = W1t; K = 64;   N = 1024; rem = bid; }
    else if (bid < 576) { W = W2; Wt = W2t; K = 1024; N = 512;  rem = bid - 64; }
    else if (bid < 832) { W = W3; Wt = W3t; K = 512;  N = 512;  rem = bid - 576; }
    else                { W = W4; Wt = W4t; K = 512;  N = 64;   rem = bid - 832; }
    int nb = N / 32;
    int k0 = (rem / nb) * 32, n0 = (rem % nb) * 32;
    const float* Wp = W + (size_t)t * K * N;
    __half* Wtp = Wt + (size_t)t * N * K;
    int x = threadIdx.x, y = threadIdx.y;   // 32 x 8
    #pragma unroll
    for (int dy = 0; dy < 32; dy += 8)
        tile[y + dy][x] = Wp[(size_t)(k0 + y + dy) * N + n0 + x];
    __syncthreads();
    #pragma unroll
    for (int dy = 0; dy < 32; dy += 8)
        Wtp[(size_t)(n0 + y + dy) * K + k0 + x] = __float2half_rn(tile[x][y + dy]);
}

// -------------------- FP16 mma GEMM + fused epilogue --------------------
// 4 warps (2x2), warp tile 64x(BN/2), 3-stage cp.async, reg double-buffered frags.
template <int BN, int MODE>
__global__ void __launch_bounds__(128, 2)
gemm_h(const __half* __restrict__ A, const __half* __restrict__ Wt,
       const float* __restrict__ bias, const float* __restrict__ gg,
       const float* __restrict__ bbe, const float* __restrict__ mm,
       const float* __restrict__ vv, void* __restrict__ Cv,
       int K, int N) {
    constexpr int BM = 128, BK = 64, STAGES = 3;
    constexpr int WN = BN / 2;
    constexpr int MT = 4;
    constexpr int NT = WN / 8;
    constexpr int STG_A = BM * BK;
    constexpr int STG   = (BM + BN) * BK;

    extern __shared__ __half smem[];
    const uint32_t sb = smem_u32(smem);

    const int tid  = threadIdx.x;
    const int wid  = tid >> 5, lane = tid & 31;
    const int grp  = lane >> 2, tig = lane & 3;
    const int wm   = wid & 1, wn = wid >> 1;
    const int t    = blockIdx.z;
    const int bm   = blockIdx.y * BM;
    const int bn   = blockIdx.x * BN;

    A  += (size_t)t * R * K;
    Wt += (size_t)t * N * K;
    bias += (size_t)t * N;
    if (MODE == 0) { gg += (size_t)t * N; bbe += (size_t)t * N; mm += (size_t)t * N; vv += (size_t)t * N; }

    const int iters = K / BK;

    auto load_tiles = [&](int it) {
        const int k0 = it * BK;
        __half* d = smem + (it % STAGES) * STG;
        uint32_t dA = smem_u32(d), dB = dA + STG_A * 2;
        #pragma unroll
        for (int p = 0; p < 8; p++) {
            int idx = p * 128 + tid;
            int r = idx >> 3, c = idx & 7;
            CP16(dA + r * 128 + ((c ^ (r & 7)) << 4),
                 A + (size_t)(bm + r) * K + k0 + c * 8);
        }
        #pragma unroll
        for (int p = 0; p < BN / 16; p++) {
            int idx = p * 128 + tid;
            int r = idx >> 3, c = idx & 7;
            CP16(dB + r * 128 + ((c ^ (r & 7)) << 4),
                 Wt + (size_t)(bn + r) * K + k0 + c * 8);
        }
    };

    float acc[MT][NT][4];
    #pragma unroll
    for (int i = 0; i < MT; i++)
        #pragma unroll
        for (int j = 0; j < NT; j++)
            acc[i][j][0] = acc[i][j][1] = acc[i][j][2] = acc[i][j][3] = 0.f;

    #pragma unroll
    for (int s = 0; s < STAGES - 1; s++) {
        if (s < iters) load_tiles(s);
        CP_COMMIT();
    }

    const int a_row = wm * 64 + (lane & 7) + ((lane >> 3) & 1) * 8;
    const int a_csel = lane >> 4;
    const int b_row = wn * WN + (lane & 7) + ((lane >> 4) & 1) * 8;
    const int b_csel = (lane >> 3) & 1;

    for (int it = 0; it < iters; ++it) {
        asm volatile("cp.async.wait_group 1;" ::: "memory");
        __syncthreads();
        {
            int nxt = it + STAGES - 1;
            if (nxt < iters) load_tiles(nxt);
            CP_COMMIT();
        }

        const uint32_t aB = sb + (it % STAGES) * STG * 2;
        const uint32_t bB = aB + STG_A * 2;

        uint32_t af[2][MT][4], bf[2][NT][2];

        auto ldf = [&](int ks, uint32_t (&afb)[MT][4], uint32_t (&bfb)[NT][2]) {
            #pragma unroll
            for (int mi = 0; mi < MT; mi++) {
                int r = a_row + mi * 16;
                int c = ks * 2 + a_csel;
                ldsm_x4(afb[mi][0], afb[mi][1], afb[mi][2], afb[mi][3],
                        aB + r * 128 + ((c ^ (r & 7)) << 4));
            }
            #pragma unroll
            for (int nb = 0; nb < NT / 2; nb++) {
                int r = b_row + nb * 16;
                int c = ks * 2 + b_csel;
                ldsm_x4(bfb[2 * nb][0], bfb[2 * nb][1], bfb[2 * nb + 1][0], bfb[2 * nb + 1][1],
                        bB + r * 128 + ((c ^ (r & 7)) << 4));
            }
        };

        ldf(0, af[0], bf[0]);
        #pragma unroll
        for (int ks = 0; ks < BK / 16; ks++) {
            if (ks + 1 < BK / 16) ldf(ks + 1, af[(ks + 1) & 1], bf[(ks + 1) & 1]);
            const int cur = ks & 1;
            #pragma unroll
            for (int mi = 0; mi < MT; mi++)
                #pragma unroll
                for (int ni = 0; ni < NT; ni++)
                    mma_f16(acc[mi][ni][0], acc[mi][ni][1], acc[mi][ni][2], acc[mi][ni][3],
                            af[cur][mi][0], af[cur][mi][1], af[cur][mi][2], af[cur][mi][3],
                            bf[cur][ni][0], bf[cur][ni][1]);
        }
    }

    // ---- epilogue
    #pragma unroll
    for (int ni = 0; ni < NT; ni++) {
        const int col = bn + wn * WN + ni * 8 + tig * 2;
        float pb0 = __ldg(&bias[col]), pb1 = __ldg(&bias[col + 1]);
        float pm0 = 0, pm1 = 0, ps0 = 0, ps1 = 0, pe0 = 0, pe1 = 0;
        if (MODE == 0) {
            pm0 = __ldg(&mm[col]);  pm1 = __ldg(&mm[col + 1]);
            ps0 = __ldg(&gg[col])     * rsqrtf(__ldg(&vv[col])     + EPS_BN);
            ps1 = __ldg(&gg[col + 1]) * rsqrtf(__ldg(&vv[col + 1]) + EPS_BN);
            pe0 = __ldg(&bbe[col]); pe1 = __ldg(&bbe[col + 1]);
        }
        #pragma unroll
        for (int mi = 0; mi < MT; mi++) {
            #pragma unroll
            for (int h = 0; h < 2; h++) {
                const int row = bm + wm * 64 + mi * 16 + grp + h * 8;
                float v0 = acc[mi][ni][h * 2 + 0] + pb0;
                float v1 = acc[mi][ni][h * 2 + 1] + pb1;
                if (MODE == 0) {
                    v0 = fmaxf(v0, 0.f); v1 = fmaxf(v1, 0.f);
                    v0 = (v0 - pm0) * ps0 + pe0;
                    v1 = (v1 - pm1) * ps1 + pe1;
                    __half2* cp = (__half2*)((__half*)Cv + (size_t)t * R * N
                                             + (size_t)row * N + col);
                    *cp = __floats2half2_rn(v0, v1);
                } else {
                    float2* cp = (float2*)((float*)Cv + (size_t)t * R * N
                                           + (size_t)row * N + col);
                    *cp = make_float2(v0, v1);
                }
            }
        }
    }
}

// -------------------- head: sigmoid + per-(b,s,ue) L2 norm + transpose (4 rows/blk)
__global__ void head_kernel(const float* __restrict__ Z, float* __restrict__ out) {
    int rl = threadIdx.x >> 6;                 // 0..3
    int row = blockIdx.x * 4 + rl;
    int o = threadIdx.x & 63;                  // o = tx*2 + u
    int b = row / SUB, s = row % SUB;

    float vr = Z[(size_t)row * 64 + o];
    float zi = Z[((size_t)R + row) * 64 + o];
    float vi = 1.f / (1.f + expf(-zi));

    float p = vr * vr + vi * vi;
    #pragma unroll
    for (int off = 2; off < 32; off <<= 1)
        p += __shfl_xor_sync(0xFFFFFFFFu, p, off);

    __shared__ float partial[4][2][2];
    int lane = o & 31, warp = o >> 5;
    if (lane < 2) partial[rl][warp][lane & 1] = p;
    __syncthreads();

    int u = o & 1, tx = o >> 1;
    float inv = rsqrtf(partial[rl][0][u] + partial[rl][1][u]);

    size_t ob = (((size_t)b * 64 + u * 32 + tx) * SUB + s) * 2;
    out[ob]     = vr * inv;
    out[ob + 1] = vi * inv;
}

// -------------------- launch --------------------
extern "C" void kernel_launch(void* const* d_in, const int* in_sizes, int n_in,
                              void* d_out, int out_size) {
    const float* V1  = (const float*)d_in[0];
    const float* V2  = (const float*)d_in[1];
    const float* W1  = (const float*)d_in[2];
    const float* b1  = (const float*)d_in[3];
    const float* g1  = (const float*)d_in[4];
    const float* be1 = (const float*)d_in[5];
    const float* m1  = (const float*)d_in[6];
    const float* v1  = (const float*)d_in[7];
    const float* W2  = (const float*)d_in[8];
    const float* b2  = (const float*)d_in[9];
    const float* g2  = (const float*)d_in[10];
    const float* be2 = (const float*)d_in[11];
    const float* m2  = (const float*)d_in[12];
    const float* v2  = (const float*)d_in[13];
    const float* W3  = (const float*)d_in[14];
    const float* b3  = (const float*)d_in[15];
    const float* g3  = (const float*)d_in[16];
    const float* be3 = (const float*)d_in[17];
    const float* m3  = (const float*)d_in[18];
    const float* v3  = (const float*)d_in[19];
    const float* W4  = (const float*)d_in[20];
    const float* b4  = (const float*)d_in[21];

    __half *X, *Abuf, *Bbuf, *W1t, *W2t, *W3t, *W4t;
    float *Z;
    cudaGetSymbolAddress((void**)&X,    g_X);
    cudaGetSymbolAddress((void**)&Z,    g_Z);
    cudaGetSymbolAddress((void**)&Abuf, g_A);
    cudaGetSymbolAddress((void**)&Bbuf, g_Bf);
    cudaGetSymbolAddress((void**)&W1t,  g_W1t);
    cudaGetSymbolAddress((void**)&W2t,  g_W2t);
    cudaGetSymbolAddress((void**)&W3t,  g_W3t);
    cudaGetSymbolAddress((void**)&W4t,  g_W4t);

    const int SMEM128 = (128 + 128) * 64 * 2 * 3;   // 98304
    const int SMEM64  = (128 +  64) * 64 * 2 * 3;   // 73728
    cudaFuncSetAttribute(gemm_h<128, 0>, cudaFuncAttributeMaxDynamicSharedMemorySize, SMEM128);
    cudaFuncSetAttribute(gemm_h<64, 1>,  cudaFuncAttributeMaxDynamicSharedMemorySize, SMEM64);

    norm_in_kernel<<<R / 4, 256>>>(V1, V2, X);

    transpose_all<<<dim3(864, 1, 2), dim3(32, 8)>>>(W1, W2, W3, W4, W1t, W2t, W3t, W4t);

    gemm_h<128, 0><<<dim3(1024 / 128, R / 128, 2), 128, SMEM128>>>(
        X,    W1t, b1, g1, be1, m1, v1, Abuf, 64, 1024);
    gemm_h<128, 0><<<dim3(512 / 128, R / 128, 2), 128, SMEM128>>>(
        Abuf, W2t, b2, g2, be2, m2, v2, Bbuf, 1024, 512);
    gemm_h<128, 0><<<dim3(512 / 128, R / 128, 2), 128, SMEM128>>>(
        Bbuf, W3t, b3, g3, be3, m3, v3, Abuf, 512, 512);
    gemm_h<64, 1><<<dim3(1, R / 128, 2), 128, SMEM64>>>(
        Abuf, W4t, b4, nullptr, nullptr, nullptr, nullptr, Z, 512, 64);

    head_kernel<<<R / 4, 256>>>(Z, (float*)d_out);
}

// round 8
// speedup vs baseline: 1.1766x; 1.0108x over previous
#include <cuda_runtime.h>
#include <cuda_fp16.h>
#include <math.h>
#include <cstdint>

#define EPS_BN 1e-3f

static constexpr int B_  = 4096;
static constexpr int TXN = 32;
static constexpr int SUB = 13;
static constexpr int R   = B_ * SUB;   // 53248 rows per tower

// -------------------- scratch (alloc-free: __device__ globals) --------------------
__device__ __half g_X [(size_t)2 * R * 64];
__device__ float  g_Z [(size_t)2 * R * 64];
__device__ __half g_A [(size_t)2 * R * 1024];
__device__ __half g_Bf[(size_t)2 * R * 512];
__device__ __half g_W1t[(size_t)2 * 1024 * 64];
__device__ __half g_W2t[(size_t)2 * 512 * 1024];
__device__ __half g_W3t[(size_t)2 * 512 * 512];
__device__ __half g_W4t[(size_t)2 * 64 * 512];

// -------------------- helpers --------------------
__device__ __forceinline__ uint32_t smem_u32(const void* p) {
    uint32_t a;
    asm("{ .reg .u64 t; cvta.to.shared.u64 t, %1; cvt.u32.u64 %0, t; }" : "=r"(a) : "l"(p));
    return a;
}
#define CP16(dst, src) \
    asm volatile("cp.async.cg.shared.global [%0], [%1], 16;" :: "r"(dst), "l"(src))
#define CP_COMMIT() asm volatile("cp.async.commit_group;" ::: "memory")

__device__ __forceinline__ void ldsm_x4(uint32_t& r0, uint32_t& r1, uint32_t& r2,
                                        uint32_t& r3, uint32_t addr) {
    asm volatile("ldmatrix.sync.aligned.m8n8.x4.shared.b16 {%0,%1,%2,%3}, [%4];"
        : "=r"(r0), "=r"(r1), "=r"(r2), "=r"(r3) : "r"(addr));
}
__device__ __forceinline__ void mma_f16(float& c0, float& c1, float& c2, float& c3,
                                        uint32_t a0, uint32_t a1, uint32_t a2, uint32_t a3,
                                        uint32_t b0, uint32_t b1) {
    asm volatile(
        "mma.sync.aligned.m16n8k16.row.col.f32.f16.f16.f32 "
        "{%0,%1,%2,%3}, {%4,%5,%6,%7}, {%8,%9}, {%0,%1,%2,%3};"
        : "+f"(c0), "+f"(c1), "+f"(c2), "+f"(c3)
        : "r"(a0), "r"(a1), "r"(a2), "r"(a3), "r"(b0), "r"(b1));
}

// -------------------- prologue: per-(b,s) input normalization (4 pairs/block) -----
__global__ void norm_in_kernel(const float* __restrict__ V1,
                               const float* __restrict__ V2,
                               __half* __restrict__ X) {
    int sub = threadIdx.x >> 6;                 // 0..3
    int pair = blockIdx.x * 4 + sub;
    int b = pair / SUB, s = pair % SUB;
    int o = threadIdx.x & 63;
    int warp = o >> 5, lane = o & 31;
    const float* V = (warp == 0) ? V1 : V2;
    int base = ((b * TXN + lane) * SUB + s) * 2;
    float c0 = V[base], c1 = V[base + 1];
    float ss = c0 * c0 + c1 * c1;
    #pragma unroll
    for (int off = 16; off; off >>= 1) ss += __shfl_xor_sync(0xFFFFFFFFu, ss, off);
    float inv = rsqrtf(ss);
    X[((size_t)0 * R + pair) * 64 + o] = __float2half_rn(c0 * inv);
    X[((size_t)1 * R + pair) * 64 + o] = __float2half_rn(c1 * inv);
}

// -------------------- merged weight transpose (all 4 layers, one launch) ----------
__global__ void transpose_all(const float* __restrict__ W1, const float* __restrict__ W2,
                              const float* __restrict__ W3, const float* __restrict__ W4,
                              __half* __restrict__ W1t, __half* __restrict__ W2t,
                              __half* __restrict__ W3t, __half* __restrict__ W4t) {
    __shared__ float tile[32][33];
    int bid = blockIdx.x, t = blockIdx.z;
    const float* W; __half* Wt; int K, N, rem;
    if (bid < 64)       { W = W1; Wt = W1t; K = 64;   N = 1024; rem = bid; }
    else if (bid < 576) { W = W2; Wt = W2t; K = 1024; N = 512;  rem = bid - 64; }
    else if (bid < 832) { W = W3; Wt = W3t; K = 512;  N = 512;  rem = bid - 576; }
    else                { W = W4; Wt = W4t; K = 512;  N = 64;   rem = bid - 832; }
    int nb = N / 32;
    int k0 = (rem / nb) * 32, n0 = (rem % nb) * 32;
    const float* Wp = W + (size_t)t * K * N;
    __half* Wtp = Wt + (size_t)t * N * K;
    int x = threadIdx.x, y = threadIdx.y;   // 32 x 8
    #pragma unroll
    for (int dy = 0; dy < 32; dy += 8)
        tile[y + dy][x] = Wp[(size_t)(k0 + y + dy) * N + n0 + x];
    __syncthreads();
    #pragma unroll
    for (int dy = 0; dy < 32; dy += 8)
        Wtp[(size_t)(n0 + y + dy) * K + k0 + x] = __float2half_rn(tile[x][y + dy]);
}

// -------------------- FP16 mma GEMM + fused epilogue --------------------
// 4 warps (2x2), warp tile 64x(BN/2), 3-stage cp.async pipeline, 128 threads.
template <int BN, int MODE>
__global__ void __launch_bounds__(128, 2)
gemm_h(const __half* __restrict__ A, const __half* __restrict__ Wt,
       const float* __restrict__ bias, const float* __restrict__ gg,
       const float* __restrict__ bbe, const float* __restrict__ mm,
       const float* __restrict__ vv, void* __restrict__ Cv,
       int K, int N) {
    constexpr int BM = 128, BK = 64, STAGES = 3;
    constexpr int WN = BN / 2;
    constexpr int MT = 4;
    constexpr int NT = WN / 8;
    constexpr int STG_A = BM * BK;
    constexpr int STG   = (BM + BN) * BK;

    extern __shared__ __half smem[];
    const uint32_t sb = smem_u32(smem);

    const int tid  = threadIdx.x;
    const int wid  = tid >> 5, lane = tid & 31;
    const int grp  = lane >> 2, tig = lane & 3;
    const int wm   = wid & 1, wn = wid >> 1;
    const int t    = blockIdx.z;
    const int bm   = blockIdx.y * BM;
    const int bn   = blockIdx.x * BN;

    A  += (size_t)t * R * K;
    Wt += (size_t)t * N * K;
    bias += (size_t)t * N;
    if (MODE == 0) { gg += (size_t)t * N; bbe += (size_t)t * N; mm += (size_t)t * N; vv += (size_t)t * N; }

    const int iters = K / BK;

    auto load_tiles = [&](int it) {
        const int k0 = it * BK;
        __half* d = smem + (it % STAGES) * STG;
        uint32_t dA = smem_u32(d), dB = dA + STG_A * 2;
        #pragma unroll
        for (int p = 0; p < 8; p++) {
            int idx = p * 128 + tid;
            int r = idx >> 3, c = idx & 7;
            CP16(dA + r * 128 + ((c ^ (r & 7)) << 4),
                 A + (size_t)(bm + r) * K + k0 + c * 8);
        }
        #pragma unroll
        for (int p = 0; p < BN / 16; p++) {
            int idx = p * 128 + tid;
            int r = idx >> 3, c = idx & 7;
            CP16(dB + r * 128 + ((c ^ (r & 7)) << 4),
                 Wt + (size_t)(bn + r) * K + k0 + c * 8);
        }
    };

    float acc[MT][NT][4];
    #pragma unroll
    for (int i = 0; i < MT; i++)
        #pragma unroll
        for (int j = 0; j < NT; j++)
            acc[i][j][0] = acc[i][j][1] = acc[i][j][2] = acc[i][j][3] = 0.f;

    #pragma unroll
    for (int s = 0; s < STAGES - 1; s++) {
        if (s < iters) load_tiles(s);
        CP_COMMIT();
    }

    // loop-invariant LDSM addressing:
    //   row term: (base_row + k*16)*128   swizzle term: ((c ^ (lane&7))<<4), same for
    //   every LDSM of a given (ks, operand) since (row&7) == (lane&7) for all tiles.
    const int s3     = lane & 7;                                   // row low bits
    const uint32_t a_rb = (uint32_t)((wm * 64 + (lane & 7) + ((lane >> 3) & 1) * 8) * 128);
    const int a_csel = lane >> 4;
    const uint32_t b_rb = (uint32_t)((wn * WN + (lane & 7) + ((lane >> 4) & 1) * 8) * 128);
    const int b_csel = (lane >> 3) & 1;

    for (int it = 0; it < iters; ++it) {
        asm volatile("cp.async.wait_group 1;" ::: "memory");
        __syncthreads();
        {
            int nxt = it + STAGES - 1;
            if (nxt < iters) load_tiles(nxt);
            CP_COMMIT();
        }

        const uint32_t aB = sb + (it % STAGES) * STG * 2;
        const uint32_t bB = aB + STG_A * 2;

        #pragma unroll
        for (int ks = 0; ks < BK / 16; ks++) {
            const uint32_t xa = (uint32_t)(((ks * 2 + a_csel) ^ s3) << 4);
            const uint32_t xb = (uint32_t)(((ks * 2 + b_csel) ^ s3) << 4);
            const uint32_t aAddr = aB + a_rb + xa;
            const uint32_t bAddr = bB + b_rb + xb;
            uint32_t af[MT][4], bf[NT][2];
            #pragma unroll
            for (int mi = 0; mi < MT; mi++)
                ldsm_x4(af[mi][0], af[mi][1], af[mi][2], af[mi][3],
                        aAddr + mi * (16 * 128));
            #pragma unroll
            for (int nb = 0; nb < NT / 2; nb++)
                ldsm_x4(bf[2 * nb][0], bf[2 * nb][1], bf[2 * nb + 1][0], bf[2 * nb + 1][1],
                        bAddr + nb * (16 * 128));
            #pragma unroll
            for (int mi = 0; mi < MT; mi++)
                #pragma unroll
                for (int ni = 0; ni < NT; ni++)
                    mma_f16(acc[mi][ni][0], acc[mi][ni][1], acc[mi][ni][2], acc[mi][ni][3],
                            af[mi][0], af[mi][1], af[mi][2], af[mi][3],
                            bf[ni][0], bf[ni][1]);
        }
    }

    // ---- epilogue
    #pragma unroll
    for (int ni = 0; ni < NT; ni++) {
        const int col = bn + wn * WN + ni * 8 + tig * 2;
        float pb0 = __ldg(&bias[col]), pb1 = __ldg(&bias[col + 1]);
        float pm0 = 0, pm1 = 0, ps0 = 0, ps1 = 0, pe0 = 0, pe1 = 0;
        if (MODE == 0) {
            pm0 = __ldg(&mm[col]);  pm1 = __ldg(&mm[col + 1]);
            ps0 = __ldg(&gg[col])     * rsqrtf(__ldg(&vv[col])     + EPS_BN);
            ps1 = __ldg(&gg[col + 1]) * rsqrtf(__ldg(&vv[col + 1]) + EPS_BN);
            pe0 = __ldg(&bbe[col]); pe1 = __ldg(&bbe[col + 1]);
        }
        #pragma unroll
        for (int mi = 0; mi < MT; mi++) {
            #pragma unroll
            for (int h = 0; h < 2; h++) {
                const int row = bm + wm * 64 + mi * 16 + grp + h * 8;
                float v0 = acc[mi][ni][h * 2 + 0] + pb0;
                float v1 = acc[mi][ni][h * 2 + 1] + pb1;
                if (MODE == 0) {
                    v0 = fmaxf(v0, 0.f); v1 = fmaxf(v1, 0.f);
                    v0 = (v0 - pm0) * ps0 + pe0;
                    v1 = (v1 - pm1) * ps1 + pe1;
                    __half2* cp = (__half2*)((__half*)Cv + (size_t)t * R * N
                                             + (size_t)row * N + col);
                    *cp = __floats2half2_rn(v0, v1);
                } else {
                    float2* cp = (float2*)((float*)Cv + (size_t)t * R * N
                                           + (size_t)row * N + col);
                    *cp = make_float2(v0, v1);
                }
            }
        }
    }
}

// -------------------- head: sigmoid + per-(b,s,ue) L2 norm + transpose (4 rows/blk)
__global__ void head_kernel(const float* __restrict__ Z, float* __restrict__ out) {
    int rl = threadIdx.x >> 6;                 // 0..3
    int row = blockIdx.x * 4 + rl;
    int o = threadIdx.x & 63;                  // o = tx*2 + u
    int b = row / SUB, s = row % SUB;

    float vr = Z[(size_t)row * 64 + o];
    float zi = Z[((size_t)R + row) * 64 + o];
    float vi = 1.f / (1.f + expf(-zi));

    float p = vr * vr + vi * vi;
    #pragma unroll
    for (int off = 2; off < 32; off <<= 1)
        p += __shfl_xor_sync(0xFFFFFFFFu, p, off);

    __shared__ float partial[4][2][2];
    int lane = o & 31, warp = o >> 5;
    if (lane < 2) partial[rl][warp][lane & 1] = p;
    __syncthreads();

    int u = o & 1, tx = o >> 1;
    float inv = rsqrtf(partial[rl][0][u] + partial[rl][1][u]);

    size_t ob = (((size_t)b * 64 + u * 32 + tx) * SUB + s) * 2;
    out[ob]     = vr * inv;
    out[ob + 1] = vi * inv;
}

// -------------------- launch --------------------
extern "C" void kernel_launch(void* const* d_in, const int* in_sizes, int n_in,
                              void* d_out, int out_size) {
    const float* V1  = (const float*)d_in[0];
    const float* V2  = (const float*)d_in[1];
    const float* W1  = (const float*)d_in[2];
    const float* b1  = (const float*)d_in[3];
    const float* g1  = (const float*)d_in[4];
    const float* be1 = (const float*)d_in[5];
    const float* m1  = (const float*)d_in[6];
    const float* v1  = (const float*)d_in[7];
    const float* W2  = (const float*)d_in[8];
    const float* b2  = (const float*)d_in[9];
    const float* g2  = (const float*)d_in[10];
    const float* be2 = (const float*)d_in[11];
    const float* m2  = (const float*)d_in[12];
    const float* v2  = (const float*)d_in[13];
    const float* W3  = (const float*)d_in[14];
    const float* b3  = (const float*)d_in[15];
    const float* g3  = (const float*)d_in[16];
    const float* be3 = (const float*)d_in[17];
    const float* m3  = (const float*)d_in[18];
    const float* v3  = (const float*)d_in[19];
    const float* W4  = (const float*)d_in[20];
    const float* b4  = (const float*)d_in[21];

    __half *X, *Abuf, *Bbuf, *W1t, *W2t, *W3t, *W4t;
    float *Z;
    cudaGetSymbolAddress((void**)&X,    g_X);
    cudaGetSymbolAddress((void**)&Z,    g_Z);
    cudaGetSymbolAddress((void**)&Abuf, g_A);
    cudaGetSymbolAddress((void**)&Bbuf, g_Bf);
    cudaGetSymbolAddress((void**)&W1t,  g_W1t);
    cudaGetSymbolAddress((void**)&W2t,  g_W2t);
    cudaGetSymbolAddress((void**)&W3t,  g_W3t);
    cudaGetSymbolAddress((void**)&W4t,  g_W4t);

    const int SMEM128 = (128 + 128) * 64 * 2 * 3;   // 98304
    const int SMEM64  = (128 +  64) * 64 * 2 * 3;   // 73728
    cudaFuncSetAttribute(gemm_h<128, 0>, cudaFuncAttributeMaxDynamicSharedMemorySize, SMEM128);
    cudaFuncSetAttribute(gemm_h<64, 1>,  cudaFuncAttributeMaxDynamicSharedMemorySize, SMEM64);

    norm_in_kernel<<<R / 4, 256>>>(V1, V2, X);

    transpose_all<<<dim3(864, 1, 2), dim3(32, 8)>>>(W1, W2, W3, W4, W1t, W2t, W3t, W4t);

    gemm_h<128, 0><<<dim3(1024 / 128, R / 128, 2), 128, SMEM128>>>(
        X,    W1t, b1, g1, be1, m1, v1, Abuf, 64, 1024);
    gemm_h<128, 0><<<dim3(512 / 128, R / 128, 2), 128, SMEM128>>>(
        Abuf, W2t, b2, g2, be2, m2, v2, Bbuf, 1024, 512);
    gemm_h<128, 0><<<dim3(512 / 128, R / 128, 2), 128, SMEM128>>>(
        Bbuf, W3t, b3, g3, be3, m3, v3, Abuf, 512, 512);
    gemm_h<64, 1><<<dim3(1, R / 128, 2), 128, SMEM64>>>(
        Abuf, W4t, b4, nullptr, nullptr, nullptr, nullptr, Z, 512, 64);

    head_kernel<<<R / 4, 256>>>(Z, (float*)d_out);
}